// round 2
// baseline (speedup 1.0000x reference)
#include <cuda_runtime.h>
#include <cstdint>

// ---------------------------------------------------------------------------
// RASP pairwise potential score.
//   out = sum over pairs i<j of masked, distance-interpolated table lookups.
// Strategy:
//   * pot2 table: (pot[d], pot[d+1]) pairs -> single aligned LDG.64 per pair.
//   * atoms packed as float4 {x,y,z, (type*21)<<10 | res}; invalid-type atoms
//     get poisoned far-away coords so the dist<20 predicate excludes them.
//   * triangular tile grid: block = 128 threads, TI=512 i-rows (IPT=4 in regs),
//     TJ=128 j-cols in shared memory. Only diagonal-straddling tiles pay the
//     per-pair i<j check.
//   * -2.7 constant applied via exact integer count of contributing pairs.
// ---------------------------------------------------------------------------

static constexpr int N_MAX   = 6144;
static constexpr int TJ      = 128;
static constexpr int TI      = 512;
static constexpr int BLOCK_T = 128;
static constexpr int IPT     = 4;
static constexpr int KSTRIDE = 85 * 85 * 21;      // 151725
static constexpr int TABLE   = 6 * 85 * 85 * 21;  // 910350

__device__ float4 g_atoms[N_MAX];
__device__ float2 g_pot2[TABLE];

// ---------------------------------------------------------------------------
__global__ void prep_atoms_kernel(const float* __restrict__ coords,
                                  const int*   __restrict__ res_ids,
                                  const int*   __restrict__ types,
                                  int n, float* __restrict__ out)
{
    int i = blockIdx.x * blockDim.x + threadIdx.x;
    if (i == 0) *out = 0.0f;                // zero the (poisoned) output
    if (i >= N_MAX) return;

    float x = 0.f, y = 0.f, z = 0.f;
    int t = -1, r = 0;
    if (i < n) {
        x = coords[3 * i + 0];
        y = coords[3 * i + 1];
        z = coords[3 * i + 2];
        t = types[i];
        r = res_ids[i];
    }
    if (t < 0) {
        // Poison: spacing 32 > 20 guarantees poisoned-poisoned pairs are also
        // excluded by the dist<20 gate.
        float p = 1.0e6f + 32.0f * (float)i;
        x = p; y = p; z = p;
        t = 0;
    }
    g_atoms[i] = make_float4(x, y, z, __int_as_float(((t * 21) << 10) | r));
}

// ---------------------------------------------------------------------------
__global__ void prep_pot_kernel(const float* __restrict__ pot, int total)
{
    int idx = blockIdx.x * blockDim.x + threadIdx.x;
    if (idx >= total) return;
    float e0 = pot[idx];
    int d = idx % 21;
    float e1 = (d < 20) ? pot[idx + 1] : e0;   // d==20 never read under mask
    g_pot2[idx] = make_float2(e0, e1);
}

// ---------------------------------------------------------------------------
__global__ __launch_bounds__(BLOCK_T)
void pair_kernel(float* __restrict__ out)
{
    __shared__ float4 sA[TJ];

    const int jBase = blockIdx.x * TJ;
    const int iBase = blockIdx.y * TI;
    // Tile entirely at-or-below the diagonal: no j>i pairs possible.
    if (jBase + TJ - 1 <= iBase) return;

    const int tid = threadIdx.x;
    sA[tid] = g_atoms[jBase + tid];          // TJ == BLOCK_T
    __syncthreads();

    float xi[IPT], yi[IPT], zi[IPT];
    int   tiB[IPT], ri[IPT], ig[IPT];
#pragma unroll
    for (int q = 0; q < IPT; q++) {
        int i = iBase + tid + q * BLOCK_T;
        ig[q] = i;
        float4 a = g_atoms[i];
        xi[q] = a.x; yi[q] = a.y; zi[q] = a.z;
        int m = __float_as_int(a.w);
        ri[q]  = m & 1023;
        tiB[q] = (m >> 10) * 85;             // (ti*21)*85 = ti*85*21
    }

    float es0 = 0.f, es1 = 0.f;
    int   cn0 = 0,   cn1 = 0;

    const bool diag = (jBase < iBase + TI);

#define PAIR_BODY(Q, ES, CN, CHECK_IJ)                                        \
    {                                                                          \
        float dx = xi[Q] - sx, dy = yi[Q] - sy, dz = zi[Q] - sz;               \
        float d2 = dx * dx + dy * dy + dz * dz;                                \
        float dist;                                                            \
        asm("sqrt.approx.f32 %0, %1;" : "=f"(dist) : "f"(d2));                 \
        int sepd = ri[Q] - rj;                                                 \
        int sep  = sepd < 0 ? -sepd : sepd;                                    \
        bool ok = (sep > 2) && (dist < 20.0f);                                 \
        if (CHECK_IJ) ok = ok && (jg > ig[Q]);                                 \
        float d0f = floorf(dist);                                              \
        int kk  = min(sep - 1, 5);                                             \
        int idx = kk * KSTRIDE + tiB[Q] + tjD + (int)d0f;                      \
        if (ok) {                                                              \
            float2 e = g_pot2[idx];                                            \
            float alpha = dist - d0f;                                          \
            ES += e.x + alpha * (e.y - e.x);                                   \
            CN += 1;                                                           \
        }                                                                      \
    }

    if (!diag) {
#pragma unroll 2
        for (int j = 0; j < TJ; j++) {
            float4 s = sA[j];
            float sx = s.x, sy = s.y, sz = s.z;
            int m = __float_as_int(s.w);
            int rj = m & 1023, tjD = m >> 10;
            int jg = jBase + j;   // dead in this branch; DCE'd by compiler
            (void)jg;
            PAIR_BODY(0, es0, cn0, false)
            PAIR_BODY(1, es1, cn1, false)
            PAIR_BODY(2, es0, cn0, false)
            PAIR_BODY(3, es1, cn1, false)
        }
    } else {
#pragma unroll 2
        for (int j = 0; j < TJ; j++) {
            float4 s = sA[j];
            float sx = s.x, sy = s.y, sz = s.z;
            int m = __float_as_int(s.w);
            int rj = m & 1023, tjD = m >> 10;
            int jg = jBase + j;
            PAIR_BODY(0, es0, cn0, true)
            PAIR_BODY(1, es1, cn1, true)
            PAIR_BODY(2, es0, cn0, true)
            PAIR_BODY(3, es1, cn1, true)
        }
    }
#undef PAIR_BODY

    // Fold -2.7 per contributing pair via the exact integer count.
    float val = (es0 + es1) - 2.7f * (float)(cn0 + cn1);
#pragma unroll
    for (int o = 16; o > 0; o >>= 1)
        val += __shfl_down_sync(0xffffffffu, val, o);

    __shared__ float wsum[BLOCK_T / 32];
    if ((tid & 31) == 0) wsum[tid >> 5] = val;
    __syncthreads();
    if (tid == 0) {
        float v = 0.f;
#pragma unroll
        for (int w = 0; w < BLOCK_T / 32; w++) v += wsum[w];
        atomicAdd(out, v);
    }
}

// ---------------------------------------------------------------------------
extern "C" void kernel_launch(void* const* d_in, const int* in_sizes, int n_in,
                              void* d_out, int out_size)
{
    const float* coords  = (const float*)d_in[0];
    const int*   res_ids = (const int*)  d_in[1];
    const int*   types   = (const int*)  d_in[2];
    const float* pot     = (const float*)d_in[3];
    float*       out     = (float*)d_out;

    int n = in_sizes[1];
    if (n > N_MAX) n = N_MAX;

    prep_atoms_kernel<<<(N_MAX + 255) / 256, 256>>>(coords, res_ids, types, n, out);

    int total = in_sizes[3] < TABLE ? in_sizes[3] : TABLE;
    prep_pot_kernel<<<(total + 255) / 256, 256>>>(pot, total);

    dim3 grid(N_MAX / TJ, N_MAX / TI);   // (48, 12); below-diagonal tiles exit
    pair_kernel<<<grid, BLOCK_T>>>(out);
}

// round 3
// speedup vs baseline: 1.1629x; 1.1629x over previous
#include <cuda_runtime.h>
#include <cstdint>

// ---------------------------------------------------------------------------
// RASP pairwise potential score — type-sorted gather-coherent version.
//
// Key insight: the score is a sum over UNORDERED pairs of a symmetric
// function, so the atom array may be arbitrarily permuted. Sorting atoms by
// RASP type makes warp-lane gather indices into pot2 collapse onto a single
// (k=5, ti, tj, :) row of 21 float2 (168 B) instead of 32 random 32B sectors,
// and consecutive j-iterations reuse the same row from L1.
//   R2 evidence: 76.3 us, consistent with ~653 MB LTS gather traffic at the
//   ~6300 B/cyc L2 cap. This version cuts that traffic ~5-20x.
// ---------------------------------------------------------------------------

static constexpr int N_MAX   = 6144;
static constexpr int T_TYPES = 85;
static constexpr int TJ      = 128;
static constexpr int TI      = 512;
static constexpr int BLOCK_T = 128;
static constexpr int IPT     = 4;
static constexpr int KSTRIDE = 85 * 85 * 21;      // 151725
static constexpr int TABLE   = 6 * 85 * 85 * 21;  // 910350

__device__ float4 g_tmp[N_MAX];     // packed, unsorted
__device__ float4 g_atoms[N_MAX];   // packed, sorted by type
__device__ int    g_hist[T_TYPES];
__device__ float2 g_pot2[TABLE];

// ---------------------------------------------------------------------------
__global__ void zero_kernel(float* __restrict__ out)
{
    int i = threadIdx.x;
    if (i < T_TYPES) g_hist[i] = 0;
    if (i == 0) *out = 0.0f;
}

// ---------------------------------------------------------------------------
// Pack atom records; poison invalid-type atoms; build global type histogram.
__global__ void pack_kernel(const float* __restrict__ coords,
                            const int*   __restrict__ res_ids,
                            const int*   __restrict__ types,
                            int n)
{
    int i = blockIdx.x * blockDim.x + threadIdx.x;
    if (i >= N_MAX) return;

    float x = 0.f, y = 0.f, z = 0.f;
    int t = -1, r = 0;
    if (i < n) {
        x = coords[3 * i + 0];
        y = coords[3 * i + 1];
        z = coords[3 * i + 2];
        t = types[i];
        r = res_ids[i];
    }
    if (t < 0) {
        // Poison: spacing 32 > 20 excludes poisoned-poisoned pairs too.
        float p = 1.0e6f + 32.0f * (float)i;
        x = p; y = p; z = p;
        t = 0;
    }
    g_tmp[i] = make_float4(x, y, z, __int_as_float(((t * 21) << 10) | r));
    atomicAdd(&g_hist[t], 1);
}

// ---------------------------------------------------------------------------
// Single block: exclusive scan of the type histogram, then scatter atoms into
// type-sorted order (order within a type is arbitrary — permutation-safe).
__global__ __launch_bounds__(1024)
void scatter_kernel()
{
    __shared__ int s_off[T_TYPES];
    int tid = threadIdx.x;

    if (tid == 0) {
        int run = 0;
        for (int t = 0; t < T_TYPES; t++) {
            s_off[t] = run;
            run += g_hist[t];
        }
    }
    __syncthreads();

    for (int i = tid; i < N_MAX; i += 1024) {
        float4 a = g_tmp[i];
        int m = __float_as_int(a.w);
        int t = (m >> 10) / 21;
        int pos = atomicAdd(&s_off[t], 1);
        g_atoms[pos] = a;
    }
}

// ---------------------------------------------------------------------------
__global__ void prep_pot_kernel(const float* __restrict__ pot, int total)
{
    int idx = blockIdx.x * blockDim.x + threadIdx.x;
    if (idx >= total) return;
    float e0 = pot[idx];
    int d = idx % 21;
    float e1 = (d < 20) ? pot[idx + 1] : e0;   // d==20 never read under mask
    g_pot2[idx] = make_float2(e0, e1);
}

// ---------------------------------------------------------------------------
__global__ __launch_bounds__(BLOCK_T)
void pair_kernel(float* __restrict__ out)
{
    __shared__ float4 sA[TJ];

    const int jBase = blockIdx.x * TJ;
    const int iBase = blockIdx.y * TI;
    // Tile entirely at-or-below the diagonal: no j>i pairs possible.
    if (jBase + TJ - 1 <= iBase) return;

    const int tid = threadIdx.x;
    sA[tid] = g_atoms[jBase + tid];          // TJ == BLOCK_T
    __syncthreads();

    float xi[IPT], yi[IPT], zi[IPT];
    int   tiB[IPT], ri[IPT], ig[IPT];
#pragma unroll
    for (int q = 0; q < IPT; q++) {
        int i = iBase + tid + q * BLOCK_T;
        ig[q] = i;
        float4 a = g_atoms[i];
        xi[q] = a.x; yi[q] = a.y; zi[q] = a.z;
        int m = __float_as_int(a.w);
        ri[q]  = m & 1023;
        tiB[q] = (m >> 10) * 85;             // (ti*21)*85 = ti*85*21
    }

    float es0 = 0.f, es1 = 0.f;
    int   cn0 = 0,   cn1 = 0;

    const bool diag = (jBase < iBase + TI);

#define PAIR_BODY(Q, ES, CN, CHECK_IJ)                                        \
    {                                                                          \
        float dx = xi[Q] - sx, dy = yi[Q] - sy, dz = zi[Q] - sz;               \
        float d2 = dx * dx + dy * dy + dz * dz;                                \
        float dist;                                                            \
        asm("sqrt.approx.f32 %0, %1;" : "=f"(dist) : "f"(d2));                 \
        int sepd = ri[Q] - rj;                                                 \
        int sep  = sepd < 0 ? -sepd : sepd;                                    \
        bool ok = (sep > 2) && (dist < 20.0f);                                 \
        if (CHECK_IJ) ok = ok && (jg > ig[Q]);                                 \
        float d0f = floorf(dist);                                              \
        int kk  = min(sep - 1, 5);                                             \
        int idx = kk * KSTRIDE + tiB[Q] + tjD + (int)d0f;                      \
        if (ok) {                                                              \
            float2 e = g_pot2[idx];                                            \
            float alpha = dist - d0f;                                          \
            ES += e.x + alpha * (e.y - e.x);                                   \
            CN += 1;                                                           \
        }                                                                      \
    }

    if (!diag) {
#pragma unroll 2
        for (int j = 0; j < TJ; j++) {
            float4 s = sA[j];
            float sx = s.x, sy = s.y, sz = s.z;
            int m = __float_as_int(s.w);
            int rj = m & 1023, tjD = m >> 10;
            int jg = jBase + j;   // dead here; DCE'd
            (void)jg;
            PAIR_BODY(0, es0, cn0, false)
            PAIR_BODY(1, es1, cn1, false)
            PAIR_BODY(2, es0, cn0, false)
            PAIR_BODY(3, es1, cn1, false)
        }
    } else {
#pragma unroll 2
        for (int j = 0; j < TJ; j++) {
            float4 s = sA[j];
            float sx = s.x, sy = s.y, sz = s.z;
            int m = __float_as_int(s.w);
            int rj = m & 1023, tjD = m >> 10;
            int jg = jBase + j;
            PAIR_BODY(0, es0, cn0, true)
            PAIR_BODY(1, es1, cn1, true)
            PAIR_BODY(2, es0, cn0, true)
            PAIR_BODY(3, es1, cn1, true)
        }
    }
#undef PAIR_BODY

    // Fold -2.7 per contributing pair via the exact integer count.
    float val = (es0 + es1) - 2.7f * (float)(cn0 + cn1);
#pragma unroll
    for (int o = 16; o > 0; o >>= 1)
        val += __shfl_down_sync(0xffffffffu, val, o);

    __shared__ float wsum[BLOCK_T / 32];
    if ((tid & 31) == 0) wsum[tid >> 5] = val;
    __syncthreads();
    if (tid == 0) {
        float v = 0.f;
#pragma unroll
        for (int w = 0; w < BLOCK_T / 32; w++) v += wsum[w];
        atomicAdd(out, v);
    }
}

// ---------------------------------------------------------------------------
extern "C" void kernel_launch(void* const* d_in, const int* in_sizes, int n_in,
                              void* d_out, int out_size)
{
    const float* coords  = (const float*)d_in[0];
    const int*   res_ids = (const int*)  d_in[1];
    const int*   types   = (const int*)  d_in[2];
    const float* pot     = (const float*)d_in[3];
    float*       out     = (float*)d_out;

    int n = in_sizes[1];
    if (n > N_MAX) n = N_MAX;

    zero_kernel<<<1, 128>>>(out);
    pack_kernel<<<(N_MAX + 255) / 256, 256>>>(coords, res_ids, types, n);
    scatter_kernel<<<1, 1024>>>();

    int total = in_sizes[3] < TABLE ? in_sizes[3] : TABLE;
    prep_pot_kernel<<<(total + 255) / 256, 256>>>(pot, total);

    dim3 grid(N_MAX / TJ, N_MAX / TI);   // (48, 12); below-diagonal tiles exit
    pair_kernel<<<grid, BLOCK_T>>>(out);
}

// round 4
// speedup vs baseline: 1.3193x; 1.1345x over previous
#include <cuda_runtime.h>
#include <cstdint>

// ---------------------------------------------------------------------------
// RASP pairwise potential score — type-sorted, branchless, exact-count.
//  * atoms sorted by type => warp-coherent pot2 gathers (L1-resident rows)
//  * branchless pair body (no BSSY/BSYNC in hot loop); gather index always
//    in-bounds via clamps, contribution masked by a SEL'd weight
//  * -2.7 per-pair constant via exact integer count, finalized in double
//  * TI=256/IPT=2 => 600 blocks (~4/SM) for latency hiding
// ---------------------------------------------------------------------------

static constexpr int N_MAX   = 6144;
static constexpr int T_TYPES = 85;
static constexpr int TJ      = 128;
static constexpr int TI      = 256;
static constexpr int BLOCK_T = 128;
static constexpr int IPT     = 2;
static constexpr int KSTRIDE = 85 * 85 * 21;      // 151725
static constexpr int TABLE   = 6 * 85 * 85 * 21;  // 910350

__device__ float4 g_tmp[N_MAX];     // packed, unsorted
__device__ float4 g_atoms[N_MAX];   // packed, sorted by type
__device__ int    g_hist[T_TYPES];
__device__ __align__(16) float2 g_pot2[TABLE];
__device__ float  g_es;
__device__ int    g_cn;

// ---------------------------------------------------------------------------
__global__ void zero_kernel()
{
    int i = threadIdx.x;
    if (i < T_TYPES) g_hist[i] = 0;
    if (i == 0) { g_es = 0.0f; g_cn = 0; }
}

// ---------------------------------------------------------------------------
// Pack atom records; poison invalid-type atoms; build global type histogram.
__global__ void pack_kernel(const float* __restrict__ coords,
                            const int*   __restrict__ res_ids,
                            const int*   __restrict__ types,
                            int n)
{
    int i = blockIdx.x * blockDim.x + threadIdx.x;
    if (i >= N_MAX) return;

    float x = 0.f, y = 0.f, z = 0.f;
    int t = -1, r = 0;
    if (i < n) {
        x = coords[3 * i + 0];
        y = coords[3 * i + 1];
        z = coords[3 * i + 2];
        t = types[i];
        r = res_ids[i];
    }
    if (t < 0) {
        // Poison: spacing 32 > 20 excludes poisoned-poisoned pairs too.
        float p = 1.0e6f + 32.0f * (float)i;
        x = p; y = p; z = p;
        t = 0;
    }
    g_tmp[i] = make_float4(x, y, z, __int_as_float(((t * 21) << 10) | r));
    atomicAdd(&g_hist[t], 1);
}

// ---------------------------------------------------------------------------
// Single block: exclusive scan of the type histogram, scatter to sorted order
// (order within a type is arbitrary — permutation-safe for a pair sum).
__global__ __launch_bounds__(1024)
void scatter_kernel()
{
    __shared__ int s_off[T_TYPES];
    int tid = threadIdx.x;

    if (tid == 0) {
        int run = 0;
        for (int t = 0; t < T_TYPES; t++) { s_off[t] = run; run += g_hist[t]; }
    }
    __syncthreads();

    for (int i = tid; i < N_MAX; i += 1024) {
        float4 a = g_tmp[i];
        int m = __float_as_int(a.w);
        int t = (m >> 10) / 21;
        int pos = atomicAdd(&s_off[t], 1);
        g_atoms[pos] = a;
    }
}

// ---------------------------------------------------------------------------
// Fused (e0, e1) table, vectorized: 4 elements / thread, float4 in/out.
__global__ void prep_pot_kernel(const float* __restrict__ pot, int total)
{
    int i4 = (blockIdx.x * blockDim.x + threadIdx.x) * 4;
    if (i4 >= total) return;

    if (i4 + 4 <= total) {
        float4 p = *reinterpret_cast<const float4*>(pot + i4);
        float  p4 = (i4 + 4 < total) ? pot[i4 + 4] : 0.0f;
        float v[5] = {p.x, p.y, p.z, p.w, p4};
        float2 o[4];
        int d = i4 % 21;
#pragma unroll
        for (int c = 0; c < 4; c++) {
            int dc = d + c; if (dc >= 21) dc -= 21;
            o[c].x = v[c];
            o[c].y = (dc < 20) ? v[c + 1] : v[c];
        }
        float4* dst = reinterpret_cast<float4*>(&g_pot2[i4]);
        dst[0] = make_float4(o[0].x, o[0].y, o[1].x, o[1].y);
        dst[1] = make_float4(o[2].x, o[2].y, o[3].x, o[3].y);
    } else {
        for (int idx = i4; idx < total; idx++) {
            float e0 = pot[idx];
            int d = idx % 21;
            float e1 = (d < 20) ? pot[idx + 1] : e0;
            g_pot2[idx] = make_float2(e0, e1);
        }
    }
}

// ---------------------------------------------------------------------------
__global__ __launch_bounds__(BLOCK_T)
void pair_kernel()
{
    __shared__ float4 sA[TJ];

    const int jBase = blockIdx.x * TJ;
    const int iBase = blockIdx.y * TI;
    if (jBase + TJ - 1 <= iBase) return;   // tile fully below diagonal

    const int tid = threadIdx.x;
    sA[tid] = g_atoms[jBase + tid];        // TJ == BLOCK_T
    __syncthreads();

    float xi[IPT], yi[IPT], zi[IPT];
    int   tiB[IPT], ri[IPT], ig[IPT];
#pragma unroll
    for (int q = 0; q < IPT; q++) {
        int i = iBase + tid + q * BLOCK_T;
        ig[q] = i;
        float4 a = g_atoms[i];
        xi[q] = a.x; yi[q] = a.y; zi[q] = a.z;
        int m = __float_as_int(a.w);
        ri[q]  = m & 1023;
        tiB[q] = (m >> 10) * 85;           // ti*21*85
    }

    float es = 0.f;
    int   cn = 0;

    const bool diag = (jBase < iBase + TI);

    // Branchless body: always-in-bounds gather + SEL'd weight. No branches.
#define PAIR_BODY(Q, CHECK_IJ)                                                \
    {                                                                          \
        float dx = xi[Q] - sx, dy = yi[Q] - sy, dz = zi[Q] - sz;               \
        float d2 = dx * dx + dy * dy + dz * dz;                                \
        float dist;                                                            \
        asm("sqrt.approx.f32 %0, %1;" : "=f"(dist) : "f"(d2));                 \
        int sepd = ri[Q] - rj;                                                 \
        int sep  = sepd < 0 ? -sepd : sepd;                                    \
        bool ok = (sep > 2) && (dist < 20.0f);                                 \
        if (CHECK_IJ) ok = ok && (jg > ig[Q]);                                 \
        float dc  = fminf(dist, 20.0f);                                        \
        float d0f = floorf(dc);                                                \
        int kk  = min(max(sep - 1, 0), 5);                                     \
        int idx = kk * KSTRIDE + tiB[Q] + tjD + (int)d0f;                      \
        float2 e = g_pot2[idx];                                                \
        float alpha = dc - d0f;                                                \
        float val = e.x + alpha * (e.y - e.x);                                 \
        float w = ok ? 1.0f : 0.0f;                                            \
        es = fmaf(w, val, es);                                                 \
        cn += (int)ok;                                                         \
    }

    if (!diag) {
#pragma unroll 4
        for (int j = 0; j < TJ; j++) {
            float4 s = sA[j];
            float sx = s.x, sy = s.y, sz = s.z;
            int m = __float_as_int(s.w);
            int rj = m & 1023, tjD = m >> 10;
            int jg = jBase + j; (void)jg;
            PAIR_BODY(0, false)
            PAIR_BODY(1, false)
        }
    } else {
#pragma unroll 4
        for (int j = 0; j < TJ; j++) {
            float4 s = sA[j];
            float sx = s.x, sy = s.y, sz = s.z;
            int m = __float_as_int(s.w);
            int rj = m & 1023, tjD = m >> 10;
            int jg = jBase + j;
            PAIR_BODY(0, true)
            PAIR_BODY(1, true)
        }
    }
#undef PAIR_BODY

    // Reduce interp-sum (float) and pair-count (int) separately.
#pragma unroll
    for (int o = 16; o > 0; o >>= 1) {
        es += __shfl_down_sync(0xffffffffu, es, o);
        cn += __shfl_down_sync(0xffffffffu, cn, o);
    }

    __shared__ float wes[BLOCK_T / 32];
    __shared__ int   wcn[BLOCK_T / 32];
    if ((tid & 31) == 0) { wes[tid >> 5] = es; wcn[tid >> 5] = cn; }
    __syncthreads();
    if (tid == 0) {
        float e = 0.f; int c = 0;
#pragma unroll
        for (int w = 0; w < BLOCK_T / 32; w++) { e += wes[w]; c += wcn[w]; }
        atomicAdd(&g_es, e);
        atomicAdd(&g_cn, c);
    }
}

// ---------------------------------------------------------------------------
__global__ void finalize_kernel(float* __restrict__ out)
{
    *out = (float)((double)g_es - 2.7 * (double)g_cn);
}

// ---------------------------------------------------------------------------
extern "C" void kernel_launch(void* const* d_in, const int* in_sizes, int n_in,
                              void* d_out, int out_size)
{
    const float* coords  = (const float*)d_in[0];
    const int*   res_ids = (const int*)  d_in[1];
    const int*   types   = (const int*)  d_in[2];
    const float* pot     = (const float*)d_in[3];
    float*       out     = (float*)d_out;

    int n = in_sizes[1];
    if (n > N_MAX) n = N_MAX;

    zero_kernel<<<1, 128>>>();
    pack_kernel<<<(N_MAX + 255) / 256, 256>>>(coords, res_ids, types, n);
    scatter_kernel<<<1, 1024>>>();

    int total = in_sizes[3] < TABLE ? in_sizes[3] : TABLE;
    int nT4 = (total + 3) / 4;
    prep_pot_kernel<<<(nT4 + 255) / 256, 256>>>(pot, total);

    dim3 grid(N_MAX / TJ, N_MAX / TI);   // (48, 24); below-diagonal tiles exit
    pair_kernel<<<grid, BLOCK_T>>>();

    finalize_kernel<<<1, 1>>>(out);
}

// round 5
// speedup vs baseline: 1.6022x; 1.2144x over previous
#include <cuda_runtime.h>
#include <cstdint>

// ---------------------------------------------------------------------------
// RASP pairwise potential score — type-sorted, original-order-correct,
// latency-optimized.
//  * atoms sorted by type => warp-coherent pot gathers (L1-resident rows)
//  * pot_tensor is NOT symmetric in (ti,tj); reference uses original-index
//    order ii<jj. We pack orig index in the atom word's top bits so one int
//    compare selects (ti,tj) vs (tj,ti). (This was the R3/R4 2.7e-4 error.)
//  * direct 2x LDG.32 gather from pot (same sector) — no fused-table prep
//  * 1D triangular grid: 1176 blocks = one near-perfect 8-blocks/SM wave
//  * 2 launches total: fused prep (1 block) + pair kernel with last-block
//    threadfence-ticket finalization
// ---------------------------------------------------------------------------

static constexpr int N_MAX   = 6144;
static constexpr int T_TYPES = 85;
static constexpr int TJ      = 128;
static constexpr int BLOCK_T = 128;
static constexpr int NTILES  = N_MAX / TJ;                 // 48
static constexpr int NWORK   = NTILES * (NTILES + 1) / 2;  // 1176
static constexpr int KSTRIDE = 85 * 85 * 21;               // 151725

__device__ float4 g_tmp[N_MAX];     // packed, unsorted
__device__ float4 g_atoms[N_MAX];   // packed, sorted by type
__device__ float  g_es;             // accumulator (zero-init; last block resets)
__device__ unsigned int g_ticket;   // block completion ticket (ditto)

// ---------------------------------------------------------------------------
// Fused prep: pack + poison + type histogram + scan + scatter. One block.
// Atom word: w = (orig_idx << 16) | (type << 9) | res_id
//   orig < 6144 (13b), type < 85 (7b), res < 307 (9b) -> 29 bits, positive.
//   Comparing packed words == comparing original indices (top field, unique).
__global__ __launch_bounds__(1024)
void prep_kernel(const float* __restrict__ coords,
                 const int*   __restrict__ res_ids,
                 const int*   __restrict__ types,
                 int n)
{
    __shared__ int s_hist[T_TYPES];
    __shared__ int s_off[T_TYPES];
    const int tid = threadIdx.x;
    constexpr int APT = N_MAX / 1024;   // 6 atoms per thread

    if (tid < T_TYPES) s_hist[tid] = 0;
    __syncthreads();

    float4 loc[APT];
    int    lt[APT];
#pragma unroll
    for (int q = 0; q < APT; q++) {
        int i = tid + q * 1024;
        float x = 0.f, y = 0.f, z = 0.f;
        int t = -1, r = 0;
        if (i < n) {
            x = coords[3 * i + 0];
            y = coords[3 * i + 1];
            z = coords[3 * i + 2];
            t = types[i];
            r = res_ids[i];
        }
        if (t < 0) {
            // Poison: spacing 32 > 20 excludes poisoned-poisoned pairs too.
            float p = 1.0e6f + 32.0f * (float)i;
            x = p; y = p; z = p;
            t = 0;
        }
        loc[q] = make_float4(x, y, z, __int_as_float((i << 16) | (t << 9) | r));
        lt[q] = t;
        atomicAdd(&s_hist[t], 1);
    }
    __syncthreads();

    if (tid == 0) {
        int run = 0;
        for (int t = 0; t < T_TYPES; t++) { s_off[t] = run; run += s_hist[t]; }
    }
    __syncthreads();

#pragma unroll
    for (int q = 0; q < APT; q++) {
        int pos = atomicAdd(&s_off[lt[q]], 1);
        g_atoms[pos] = loc[q];
    }
}

// ---------------------------------------------------------------------------
__global__ __launch_bounds__(BLOCK_T)
void pair_kernel(const float* __restrict__ pot, float* __restrict__ out)
{
    // Triangular decode: bid -> (iT, jT), jT >= iT.  S(i) = (97i - i^2)/2.
    const int bid = blockIdx.x;
    int iT = (int)((97.0f - sqrtf(9409.0f - 8.0f * (float)bid)) * 0.5f);
#define TRI_S(i) (((97 * (i)) - (i) * (i)) / 2)
    while (TRI_S(iT + 1) <= bid) iT++;
    while (TRI_S(iT) > bid) iT--;
    const int jT = iT + (bid - TRI_S(iT));
#undef TRI_S

    __shared__ float4 sA[TJ];
    const int tid = threadIdx.x;
    sA[tid] = g_atoms[jT * TJ + tid];
    __syncthreads();

    float4 a = g_atoms[iT * TJ + tid];
    const float xi = a.x, yi = a.y, zi = a.z;
    const int mi = __float_as_int(a.w);
    const int ri = mi & 511;
    const int ti21 = ((mi >> 9) & 127) * 21;
    const int ti1785 = ti21 * 85;

    float es = 0.f;

    // Branchless pair body. Gather index always in-bounds (d0 clamped to 19,
    // so idx+1 stays inside the table); contribution masked by SEL'd weight.
    // Type-order: original-index order via packed-word compare (mi < mj).
#define PAIR_BODY(CHECK_IJ)                                                    \
    {                                                                          \
        float4 s = sA[j];                                                      \
        float dx = xi - s.x, dy = yi - s.y, dz = zi - s.z;                     \
        float d2 = dx * dx + dy * dy + dz * dz;                                \
        float dist;                                                            \
        asm("sqrt.approx.f32 %0, %1;" : "=f"(dist) : "f"(d2));                 \
        int mj = __float_as_int(s.w);                                          \
        int rj = mj & 511;                                                     \
        int tj21 = ((mj >> 9) & 127) * 21;                                     \
        int tj1785 = tj21 * 85;                                                \
        int sepd = ri - rj;                                                    \
        int sep = sepd < 0 ? -sepd : sepd;                                     \
        bool ok = (sep > 2) && (dist < 20.0f);                                 \
        if (CHECK_IJ) ok = ok && (j > tid);                                    \
        bool sw = mi < mj;  /* orig(i) < orig(j) */                            \
        int termi = sw ? ti1785 : ti21;                                        \
        int termj = sw ? tj21 : tj1785;                                        \
        float dc = fminf(dist, 20.0f);                                         \
        float d0f = floorf(dc);                                                \
        int d0i = min((int)d0f, 19);                                           \
        int kk = min(max(sep - 1, 0), 5);                                      \
        int idx = kk * KSTRIDE + termi + termj + d0i;                          \
        float e0 = __ldg(pot + idx);                                           \
        float e1 = __ldg(pot + idx + 1);                                       \
        float alpha = dc - d0f;                                                \
        float val = fmaf(alpha, e1 - e0, e0) - 2.7f;                           \
        float w = ok ? 1.0f : 0.0f;                                            \
        es = fmaf(w, val, es);                                                 \
    }

    if (iT != jT) {
#pragma unroll 4
        for (int j = 0; j < TJ; j++) PAIR_BODY(false)
    } else {
#pragma unroll 4
        for (int j = 0; j < TJ; j++) PAIR_BODY(true)
    }
#undef PAIR_BODY

    // Block reduction.
#pragma unroll
    for (int o = 16; o > 0; o >>= 1)
        es += __shfl_down_sync(0xffffffffu, es, o);

    __shared__ float wes[BLOCK_T / 32];
    if ((tid & 31) == 0) wes[tid >> 5] = es;
    __syncthreads();

    if (tid == 0) {
        float e = 0.f;
#pragma unroll
        for (int w = 0; w < BLOCK_T / 32; w++) e += wes[w];

        atomicAdd(&g_es, e);
        __threadfence();
        unsigned int t = atomicAdd(&g_ticket, 1u);
        if (t == (unsigned int)(NWORK - 1)) {
            // All blocks' g_es adds are fenced before their tickets; we saw
            // the last ticket, so a fresh read sees the full sum.
            __threadfence();
            float total = *(volatile float*)&g_es;
            *out = total;
            g_es = 0.0f;          // reset for the next graph replay
            g_ticket = 0u;
        }
    }
}

// ---------------------------------------------------------------------------
extern "C" void kernel_launch(void* const* d_in, const int* in_sizes, int n_in,
                              void* d_out, int out_size)
{
    const float* coords  = (const float*)d_in[0];
    const int*   res_ids = (const int*)  d_in[1];
    const int*   types   = (const int*)  d_in[2];
    const float* pot     = (const float*)d_in[3];
    float*       out     = (float*)d_out;

    int n = in_sizes[1];
    if (n > N_MAX) n = N_MAX;

    prep_kernel<<<1, 1024>>>(coords, res_ids, types, n);
    pair_kernel<<<NWORK, BLOCK_T>>>(pot, out);
}

// round 6
// speedup vs baseline: 1.6742x; 1.0449x over previous
#include <cuda_runtime.h>
#include <cstdint>

// ---------------------------------------------------------------------------
// RASP pairwise score — type-sorted, order-correct, occupancy-optimized.
//  R5 evidence: pair kernel 41 us @ occ 38%, issue 58%, alu 38% -> stall-
//  limited. R6: 2x grid via j-split (15.9 blocks/SM), j-meta pre-unpacked in
//  smem (-4 alu/body), parallel prep scan.
// ---------------------------------------------------------------------------

static constexpr int N_MAX   = 6144;
static constexpr int T_TYPES = 85;
static constexpr int TJ      = 128;
static constexpr int HJ      = 64;                          // j per block
static constexpr int BLOCK_T = 128;
static constexpr int NTILES  = N_MAX / TJ;                  // 48
static constexpr int NWORK   = NTILES * (NTILES + 1) / 2;   // 1176
static constexpr int NBLK    = NWORK * 2;                   // 2352
static constexpr int KSTRIDE = 85 * 85 * 21;                // 151725

__device__ float4 g_atoms[N_MAX];   // sorted coords (w unused)
__device__ int4   g_meta[N_MAX];    // {res, t*21, t*1785, orig_idx}
__device__ float  g_es;             // zero-init; last block resets
__device__ unsigned int g_ticket;

// ---------------------------------------------------------------------------
// Fused prep: pack + poison + histogram + parallel scan + scatter. One block.
__global__ __launch_bounds__(1024)
void prep_kernel(const float* __restrict__ coords,
                 const int*   __restrict__ res_ids,
                 const int*   __restrict__ types,
                 int n)
{
    __shared__ int s_hist[T_TYPES];
    __shared__ int s_scan[128];
    __shared__ int s_off[T_TYPES];
    const int tid = threadIdx.x;
    constexpr int APT = N_MAX / 1024;   // 6

    if (tid < T_TYPES) s_hist[tid] = 0;
    __syncthreads();

    float4 lc[APT];
    int    lt[APT], lr[APT];
#pragma unroll
    for (int q = 0; q < APT; q++) {
        int i = tid + q * 1024;
        float x = 0.f, y = 0.f, z = 0.f;
        int t = -1, r = 0;
        if (i < n) {
            x = coords[3 * i + 0];
            y = coords[3 * i + 1];
            z = coords[3 * i + 2];
            t = types[i];
            r = res_ids[i];
        }
        if (t < 0) {
            // Poison: spacing 32 > 20 also excludes poisoned-poisoned pairs.
            float p = 1.0e6f + 32.0f * (float)i;
            x = p; y = p; z = p;
            t = 0;
        }
        lc[q] = make_float4(x, y, z, 0.f);
        lt[q] = t; lr[q] = r;
        atomicAdd(&s_hist[t], 1);
    }
    __syncthreads();

    // Parallel exclusive scan over 85 bins (Hillis-Steele on 128 slots).
    if (tid < 128) {
        int v = (tid < T_TYPES) ? s_hist[tid] : 0;
        s_scan[tid] = v;
    }
    __syncthreads();
#pragma unroll
    for (int off = 1; off < 128; off <<= 1) {
        int v = 0;
        if (tid < 128) {
            v = s_scan[tid];
            if (tid >= off) v += s_scan[tid - off];
        }
        __syncthreads();
        if (tid < 128) s_scan[tid] = v;
        __syncthreads();
    }
    if (tid < T_TYPES) s_off[tid] = s_scan[tid] - s_hist[tid];  // exclusive
    __syncthreads();

#pragma unroll
    for (int q = 0; q < APT; q++) {
        int i = tid + q * 1024;
        int t = lt[q];
        int pos = atomicAdd(&s_off[t], 1);
        g_atoms[pos] = lc[q];
        g_meta[pos]  = make_int4(lr[q], t * 21, t * 1785, i);
    }
}

// ---------------------------------------------------------------------------
__global__ __launch_bounds__(BLOCK_T, 12)
void pair_kernel(const float* __restrict__ pot, float* __restrict__ out)
{
    // Triangular decode on blockIdx.x: bid -> (iT, jT), jT >= iT.
    const int bid = blockIdx.x;
    int iT = (int)((97.0f - sqrtf(9409.0f - 8.0f * (float)bid)) * 0.5f);
#define TRI_S(i) (((97 * (i)) - (i) * (i)) / 2)
    while (TRI_S(iT + 1) <= bid) iT++;
    while (TRI_S(iT) > bid) iT--;
    const int jT = iT + (bid - TRI_S(iT));
#undef TRI_S
    const int hbase = blockIdx.y * HJ;    // which half of the j-tile

    __shared__ float4 sA[HJ];
    __shared__ int4   sM[HJ];
    const int tid = threadIdx.x;
    if (tid < HJ) {
        sA[tid] = g_atoms[jT * TJ + hbase + tid];
    } else {
        sM[tid - HJ] = g_meta[jT * TJ + hbase + (tid - HJ)];
    }
    __syncthreads();

    const float4 a  = g_atoms[iT * TJ + tid];
    const int4   im = g_meta [iT * TJ + tid];
    const float xi = a.x, yi = a.y, zi = a.z;
    const int ri = im.x, ti21 = im.y, ti1785 = im.z, oi = im.w;

    float es0 = 0.f, es1 = 0.f;

    // Branchless body; gather always in-bounds (d0 clamped to 19);
    // (ti,tj) order chosen by ORIGINAL index compare (pot not symmetric).
#define PAIR_BODY(J, ES, CHECK_IJ)                                             \
    {                                                                          \
        float4 s = sA[J];                                                      \
        int4   m = sM[J];                                                      \
        float dx = xi - s.x, dy = yi - s.y, dz = zi - s.z;                     \
        float d2 = dx * dx + dy * dy + dz * dz;                                \
        float dist;                                                            \
        asm("sqrt.approx.f32 %0, %1;" : "=f"(dist) : "f"(d2));                 \
        int sepd = ri - m.x;                                                   \
        int sep  = sepd < 0 ? -sepd : sepd;                                    \
        bool ok = (sep > 2) && (dist < 20.0f);                                 \
        if (CHECK_IJ) ok = ok && (hbase + (J) > tid);                          \
        bool sw = oi < m.w;                                                    \
        int termi = sw ? ti1785 : ti21;                                        \
        int termj = sw ? m.y : m.z;                                            \
        float dc  = fminf(dist, 20.0f);                                        \
        int   d0i = min((int)dc, 19);                                          \
        float d0f = (float)d0i;                                                \
        float alpha = dc - d0f;                                                \
        int kk  = min(max(sep - 1, 0), 5);                                     \
        int idx = kk * KSTRIDE + termi + termj + d0i;                          \
        float e0 = __ldg(pot + idx);                                           \
        float e1 = __ldg(pot + idx + 1);                                       \
        float val = fmaf(alpha, e1 - e0, e0) - 2.7f;                           \
        float w = ok ? 1.0f : 0.0f;                                            \
        ES = fmaf(w, val, ES);                                                 \
    }

    if (iT != jT) {
#pragma unroll 4
        for (int j = 0; j < HJ; j += 2) {
            PAIR_BODY(j,     es0, false)
            PAIR_BODY(j + 1, es1, false)
        }
    } else {
#pragma unroll 4
        for (int j = 0; j < HJ; j += 2) {
            PAIR_BODY(j,     es0, true)
            PAIR_BODY(j + 1, es1, true)
        }
    }
#undef PAIR_BODY

    float es = es0 + es1;
#pragma unroll
    for (int o = 16; o > 0; o >>= 1)
        es += __shfl_down_sync(0xffffffffu, es, o);

    __shared__ float wes[BLOCK_T / 32];
    if ((tid & 31) == 0) wes[tid >> 5] = es;
    __syncthreads();

    if (tid == 0) {
        float e = 0.f;
#pragma unroll
        for (int w = 0; w < BLOCK_T / 32; w++) e += wes[w];

        atomicAdd(&g_es, e);
        __threadfence();
        unsigned int t = atomicAdd(&g_ticket, 1u);
        if (t == (unsigned int)(NBLK - 1)) {
            __threadfence();
            *out = *(volatile float*)&g_es;
            g_es = 0.0f;          // reset for next graph replay
            g_ticket = 0u;
        }
    }
}

// ---------------------------------------------------------------------------
extern "C" void kernel_launch(void* const* d_in, const int* in_sizes, int n_in,
                              void* d_out, int out_size)
{
    const float* coords  = (const float*)d_in[0];
    const int*   res_ids = (const int*)  d_in[1];
    const int*   types   = (const int*)  d_in[2];
    const float* pot     = (const float*)d_in[3];
    float*       out     = (float*)d_out;

    int n = in_sizes[1];
    if (n > N_MAX) n = N_MAX;

    prep_kernel<<<1, 1024>>>(coords, res_ids, types, n);

    dim3 grid(NWORK, 2);
    pair_kernel<<<grid, BLOCK_T>>>(pot, out);
}